// round 7
// baseline (speedup 1.0000x reference)
#include <cuda_runtime.h>

#define BB 4
#define CC 12
#define HH0 512
#define NBC (BB*CC)          // 48
#define NSCALES 5
#define TSY 32               // output tile rows
#define TSX 64               // output tile cols
#define TINY 42              // TSY + 10
#define TINX 74              // TSX + 10
#define SXP 75               // sx/sy pitch
#define HBPI 68              // hb pitch (mult of 4 -> float4 aligned)
#define NTHR 256

__device__ float g_x0[(size_t)NBC*HH0*HH0];
__device__ float g_px1[(size_t)NBC*256*256];
__device__ float g_py1[(size_t)NBC*256*256];
__device__ float g_px2[(size_t)NBC*128*128];
__device__ float g_py2[(size_t)NBC*128*128];
__device__ float g_px3[(size_t)NBC*64*64];
__device__ float g_py3[(size_t)NBC*64*64];
__device__ float g_px4[(size_t)NBC*32*32];
__device__ float g_py4[(size_t)NBC*32*32];
__device__ float g_ss[NSCALES*NBC];
__device__ float g_cs[NSCALES*NBC];

// Device-side symbol resolution (never pass these from host code!).
__device__ __forceinline__ const float* src_x(int s) {
    switch (s) { case 0: return g_x0;  case 1: return g_px1; case 2: return g_px2;
                 case 3: return g_px3; default: return g_px4; }
}
__device__ __forceinline__ const float* src_y(int s) {
    switch (s) { case 1: return g_py1; case 2: return g_py2;
                 case 3: return g_py3; default: return g_py4; }
}
__device__ __forceinline__ float* dst_x(int s) {
    switch (s) { case 0: return g_px1; case 1: return g_px2;
                 case 2: return g_px3; default: return g_px4; }
}
__device__ __forceinline__ float* dst_y(int s) {
    switch (s) { case 0: return g_py1; case 1: return g_py2;
                 case 2: return g_py3; default: return g_py4; }
}

#define SMEM_FLOATS_S0 (2*TINY*SXP + 4*TINY*HBPI)
#define SMEM_FLOATS_SN (2*TINY*SXP + 5*TINY*HBPI)

// ---------------------------------------------------------------------------
__global__ __launch_bounds__(256) void softmax_x0(
    const float* __restrict__ pred, const int* __restrict__ tgt)
{
    if (blockIdx.x == 0 && threadIdx.x < NSCALES*NBC) {
        g_ss[threadIdx.x] = 0.f; g_cs[threadIdx.x] = 0.f;
    }
    const int HW = HH0*HH0;
    int p = blockIdx.x*blockDim.x + threadIdx.x;
    if (p >= BB*HW) return;
    int b  = p / HW;
    int hw = p - b*HW;
    const float* pp = pred + (size_t)b*CC*HW + hw;

    float v[CC];
    float mx = -1e30f;
#pragma unroll
    for (int c = 0; c < CC; c++) { v[c] = pp[(size_t)c*HW]; mx = fmaxf(mx, v[c]); }
    float s = 0.f;
#pragma unroll
    for (int c = 0; c < CC; c++) { v[c] = expf(v[c]-mx); s += v[c]; }
    float inv = 1.f/s;
    size_t base = (size_t)b*CC*HW + hw;
#pragma unroll
    for (int c = 0; c < CC; c++) g_x0[base + (size_t)c*HW] = v[c]*inv;
}

// ---------------------------------------------------------------------------
// Unified SSIM tile kernel, all scales. 64x32 output tiles, fused 2x2 pooling.
// S0: y derived from tgt one-hot; conv(y^2) == conv(y) so the yy plane drops.
template<bool S0>
__global__ __launch_bounds__(NTHR) void ssim_kernel(
    const int* __restrict__ tgt, int Hs, int sidx)
{
    extern __shared__ float dsm[];
    __shared__ float rss[NTHR/32], rcs[NTHR/32];
    float* sxm = dsm;                       // [TINY][SXP]
    float* sym = sxm + TINY*SXP;
    float* hb0 = sym + TINY*SXP;            // [TINY][HBPI]
    float* hb1 = hb0 + TINY*HBPI;
    float* hb2 = hb1 + TINY*HBPI;
    float* hb4 = hb2 + TINY*HBPI;
    float* hb3 = hb4 + TINY*HBPI;           // only allocated when !S0

    const int OH = Hs - 10;
    int bc  = blockIdx.z;
    int tid = threadIdx.x;
    int ty0 = blockIdx.y*TSY, tx0 = blockIdx.x*TSX;
    const float* xp = src_x(sidx) + (size_t)bc*Hs*Hs;
    const float* yp = S0 ? nullptr : (src_y(sidx) + (size_t)bc*Hs*Hs);
    const int*   tp = S0 ? (tgt + (size_t)(bc/CC)*Hs*Hs) : nullptr;
    int cls = bc % CC;

    constexpr float G[11] = {0.00102838f,0.00759870f,0.03600080f,0.10936070f,
                             0.21300560f,0.26601180f,0.21300560f,0.10936070f,
                             0.03600080f,0.00759870f,0.00102838f};

    // Load (TINY x TINX) tile, zero-fill outside.
    for (int i = tid; i < TINY*TINX; i += NTHR) {
        int r = i / TINX, c = i - r*TINX;
        int ih = ty0 + r, iw = tx0 + c;
        float xv = 0.f, yv = 0.f;
        if (ih < Hs && iw < Hs) {
            int o = ih*Hs + iw;
            xv = xp[o];
            yv = S0 ? ((tp[o] == cls) ? 1.f : 0.f) : yp[o];
        }
        sxm[r*SXP + c] = xv; sym[r*SXP + c] = yv;
    }
    __syncthreads();

    // Fused 2x2 pooling of this tile's 32x64 region -> next scale.
    if (sidx < 4) {
        int Hd = Hs >> 1;
        float* xo = dst_x(sidx) + (size_t)bc*Hd*Hd;
        float* yo = dst_y(sidx) + (size_t)bc*Hd*Hd;
        int ph0 = blockIdx.y*16, pw0 = blockIdx.x*32;
        for (int i = tid; i < 512; i += NTHR) {
            int pr = i >> 5, pc = i & 31;
            int r = pr*2, c = pc*2;
            float px = (sxm[r*SXP+c]+sxm[r*SXP+c+1]+sxm[(r+1)*SXP+c]+sxm[(r+1)*SXP+c+1])*0.25f;
            float py = (sym[r*SXP+c]+sym[r*SXP+c+1]+sym[(r+1)*SXP+c]+sym[(r+1)*SXP+c+1])*0.25f;
            int po = (ph0+pr)*Hd + (pw0+pc);
            xo[po] = px; yo[po] = py;
        }
    }

    // Stage 1: horizontal blur, strips of 4 cols. 672 tasks.
    for (int task = tid; task < TINY*16; task += NTHR) {
        int r  = task >> 4;
        int c0 = (task & 15) << 2;
        float a0[4]={0,0,0,0}, a1[4]={0,0,0,0}, a2[4]={0,0,0,0};
        float a3[4]={0,0,0,0}, a4[4]={0,0,0,0};
        const float* sxr = sxm + r*SXP + c0;
        const float* syr = sym + r*SXP + c0;
#pragma unroll
        for (int i = 0; i < 14; i++) {
            float x = sxr[i], y = syr[i];
            float xx = x*x, xy = x*y;
            float yy = S0 ? 0.f : y*y;
#pragma unroll
            for (int j = 0; j < 4; j++) {
                int k = i - j;
                if (k >= 0 && k < 11) {
                    a0[j] = fmaf(G[k], x,  a0[j]);
                    a1[j] = fmaf(G[k], y,  a1[j]);
                    a2[j] = fmaf(G[k], xx, a2[j]);
                    if (!S0) a3[j] = fmaf(G[k], yy, a3[j]);
                    a4[j] = fmaf(G[k], xy, a4[j]);
                }
            }
        }
        int o = r*HBPI + c0;
        *(float4*)(hb0+o) = make_float4(a0[0],a0[1],a0[2],a0[3]);
        *(float4*)(hb1+o) = make_float4(a1[0],a1[1],a1[2],a1[3]);
        *(float4*)(hb2+o) = make_float4(a2[0],a2[1],a2[2],a2[3]);
        *(float4*)(hb4+o) = make_float4(a4[0],a4[1],a4[2],a4[3]);
        if (!S0) *(float4*)(hb3+o) = make_float4(a3[0],a3[1],a3[2],a3[3]);
    }
    __syncthreads();

    // Stage 2: vertical blur + SSIM, strips of 4 rows. 512 tasks.
    float lss = 0.f, lcs = 0.f;
    for (int task = tid; task < 8*TSX; task += NTHR) {
        int c  = task & 63;
        int r0 = (task >> 6) << 2;
        float m1[4]={0,0,0,0}, m2[4]={0,0,0,0}, e11[4]={0,0,0,0};
        float e22[4]={0,0,0,0}, e12[4]={0,0,0,0};
#pragma unroll
        for (int i = 0; i < 14; i++) {
            int o = (r0+i)*HBPI + c;
            float v0 = hb0[o], v1 = hb1[o], v2 = hb2[o], v4 = hb4[o];
            float v3 = S0 ? 0.f : hb3[o];
#pragma unroll
            for (int j = 0; j < 4; j++) {
                int k = i - j;
                if (k >= 0 && k < 11) {
                    m1[j]  = fmaf(G[k], v0, m1[j]);
                    m2[j]  = fmaf(G[k], v1, m2[j]);
                    e11[j] = fmaf(G[k], v2, e11[j]);
                    if (!S0) e22[j] = fmaf(G[k], v3, e22[j]);
                    e12[j] = fmaf(G[k], v4, e12[j]);
                }
            }
        }
        int ow = tx0 + c;
#pragma unroll
        for (int j = 0; j < 4; j++) {
            int oh = ty0 + r0 + j;
            if (oh < OH && ow < OH) {
                float M1 = m1[j], M2 = m2[j];
                float E22 = S0 ? M2 : e22[j];
                float m11 = M1*M1, m22 = M2*M2, m12 = M1*M2;
                float v1 = e11[j] - m11, v2 = E22 - m22, cov = e12[j] - m12;
                float cs = __fdividef(2.f*cov + 0.0009f, v1 + v2 + 0.0009f);
                float sv = __fdividef(2.f*m12 + 0.0001f, m11 + m22 + 0.0001f) * cs;
                lss += sv; lcs += cs;
            }
        }
    }

#pragma unroll
    for (int o = 16; o; o >>= 1) {
        lss += __shfl_down_sync(0xffffffffu, lss, o);
        lcs += __shfl_down_sync(0xffffffffu, lcs, o);
    }
    if ((tid & 31) == 0) { rss[tid>>5] = lss; rcs[tid>>5] = lcs; }
    __syncthreads();
    if (tid == 0) {
        float ts = 0.f, tc = 0.f;
#pragma unroll
        for (int w = 0; w < NTHR/32; w++) { ts += rss[w]; tc += rcs[w]; }
        atomicAdd(&g_ss[sidx*NBC + bc], ts);
        atomicAdd(&g_cs[sidx*NBC + bc], tc);
    }
}

// ---------------------------------------------------------------------------
__global__ void finalize(float* __restrict__ out)
{
    __shared__ float sm[NBC];
    int t = threadIdx.x;
    const float Wt[5]  = {0.0448f, 0.2856f, 0.3001f, 0.2363f, 0.1333f};
    const float cnt[5] = {502.f*502.f, 246.f*246.f, 118.f*118.f, 54.f*54.f, 22.f*22.f};
    if (t < NBC) {
        float ms = 1.f;
#pragma unroll
        for (int s = 0; s < NSCALES; s++) {
            float acc = (s == NSCALES-1) ? g_ss[s*NBC + t] : g_cs[s*NBC + t];
            float v = fmaxf(acc / cnt[s], 0.f);
            ms *= powf(v, Wt[s]);
        }
        sm[t] = ms;
    }
    __syncthreads();
    if (t == 0) {
        float a = 0.f;
#pragma unroll
        for (int i = 0; i < NBC; i++) a += sm[i];
        out[0] = 1.f - a / (float)NBC;
    }
}

// ---------------------------------------------------------------------------
extern "C" void kernel_launch(void* const* d_in, const int* in_sizes, int n_in,
                              void* d_out, int out_size)
{
    const float* pred = (const float*)d_in[0];
    const int*   tgt  = (const int*)d_in[1];
    float*       out  = (float*)d_out;

    const int smem_s0 = SMEM_FLOATS_S0*4;   // ~70.9 KB
    const int smem_sn = SMEM_FLOATS_SN*4;   // ~82.3 KB
    cudaFuncSetAttribute(ssim_kernel<true>,
        cudaFuncAttributeMaxDynamicSharedMemorySize, smem_s0);
    cudaFuncSetAttribute(ssim_kernel<false>,
        cudaFuncAttributeMaxDynamicSharedMemorySize, smem_sn);

    int np = BB*HH0*HH0;
    softmax_x0<<<(np + 255)/256, 256>>>(pred, tgt);

    // Scale 0: H=512  -> grid (8,16,48)
    { dim3 g(8, 16, NBC); ssim_kernel<true ><<<g, NTHR, smem_s0>>>(tgt, 512, 0); }
    // Scale 1: H=256  -> grid (4,8,48)
    { dim3 g(4, 8,  NBC); ssim_kernel<false><<<g, NTHR, smem_sn>>>(tgt, 256, 1); }
    // Scale 2: H=128  -> grid (2,4,48)
    { dim3 g(2, 4,  NBC); ssim_kernel<false><<<g, NTHR, smem_sn>>>(tgt, 128, 2); }
    // Scale 3: H=64   -> grid (1,2,48)
    { dim3 g(1, 2,  NBC); ssim_kernel<false><<<g, NTHR, smem_sn>>>(tgt, 64, 3); }
    // Scale 4: H=32   -> grid (1,1,48)
    { dim3 g(1, 1,  NBC); ssim_kernel<false><<<g, NTHR, smem_sn>>>(tgt, 32, 4); }

    finalize<<<1, 64>>>(out);
}

// round 8
// speedup vs baseline: 1.5092x; 1.5092x over previous
#include <cuda_runtime.h>

#define BB 4
#define CC 12
#define HH0 512
#define NBC (BB*CC)          // 48
#define NSCALES 5
#define TS 32
#define TIN 42               // TS + 10
#define SPITCH 43
#define HPITCH 33
#define NTHR 256

__device__ float g_x0[(size_t)NBC*HH0*HH0];
__device__ float g_px1[(size_t)NBC*256*256];
__device__ float g_py1[(size_t)NBC*256*256];
__device__ float g_px2[(size_t)NBC*128*128];
__device__ float g_py2[(size_t)NBC*128*128];
__device__ float g_px3[(size_t)NBC*64*64];
__device__ float g_py3[(size_t)NBC*64*64];
__device__ float g_px4[(size_t)NBC*32*32];
__device__ float g_py4[(size_t)NBC*32*32];
__device__ float g_ss[NSCALES*NBC];
__device__ float g_cs[NSCALES*NBC];

__device__ __forceinline__ const float* pool_x(int s) {
    switch (s) { case 1: return g_px1; case 2: return g_px2;
                 case 3: return g_px3; default: return g_px4; }
}
__device__ __forceinline__ const float* pool_y(int s) {
    switch (s) { case 1: return g_py1; case 2: return g_py2;
                 case 3: return g_py3; default: return g_py4; }
}

// ---------------------------------------------------------------------------
__global__ __launch_bounds__(256) void softmax_x0(
    const float* __restrict__ pred)
{
    if (blockIdx.x == 0 && threadIdx.x < NSCALES*NBC) {
        g_ss[threadIdx.x] = 0.f; g_cs[threadIdx.x] = 0.f;
    }
    const int HW = HH0*HH0;
    int p = blockIdx.x*blockDim.x + threadIdx.x;
    if (p >= BB*HW) return;
    int b  = p / HW;
    int hw = p - b*HW;
    const float* pp = pred + (size_t)b*CC*HW + hw;

    float v[CC];
    float mx = -1e30f;
#pragma unroll
    for (int c = 0; c < CC; c++) { v[c] = pp[(size_t)c*HW]; mx = fmaxf(mx, v[c]); }
    float s = 0.f;
#pragma unroll
    for (int c = 0; c < CC; c++) { v[c] = expf(v[c]-mx); s += v[c]; }
    float inv = 1.f/s;
    size_t base = (size_t)b*CC*HW + hw;
#pragma unroll
    for (int c = 0; c < CC; c++) g_x0[base + (size_t)c*HW] = v[c]*inv;
}

// ---------------------------------------------------------------------------
// Pool pyramid: each block takes a 64x64 region of (bc, scale0) and produces
// the corresponding 32x32 / 16x16 / 8x8 / 4x4 pooled blocks for scales 1..4,
// for both x (from g_x0) and y (one-hot from tgt; pools of one-hot are exact).
__global__ __launch_bounds__(NTHR) void pool_pyramid(const int* __restrict__ tgt)
{
    __shared__ float xa[64*65], ya[64*65];
    __shared__ float xb[32*33], yb[32*33];
    __shared__ float xc[16*17], yc[16*17];
    __shared__ float xd[8*9],  yd[8*9];

    int bc = blockIdx.z;
    int b  = bc / CC, cls = bc % CC;
    int oy = blockIdx.y*64, ox = blockIdx.x*64;
    int tid = threadIdx.x;

    const float* xp = g_x0 + (size_t)bc*HH0*HH0;
    const int*   tp = tgt  + (size_t)b*HH0*HH0;

    for (int i = tid; i < 64*64; i += NTHR) {
        int r = i >> 6, c = i & 63;
        int o = (oy+r)*HH0 + (ox+c);
        xa[r*65 + c] = xp[o];
        ya[r*65 + c] = (tp[o] == cls) ? 1.f : 0.f;
    }
    __syncthreads();

    // L1: 32x32 -> scale1 global + smem
    {
        float* gx = (float*)g_px1 + (size_t)bc*256*256;
        float* gy = (float*)g_py1 + (size_t)bc*256*256;
        int o1y = oy >> 1, o1x = ox >> 1;
        for (int i = tid; i < 32*32; i += NTHR) {
            int r = i >> 5, c = i & 31;
            int s0 = (2*r)*65 + 2*c;
            float px = (xa[s0]+xa[s0+1]+xa[s0+65]+xa[s0+66])*0.25f;
            float py = (ya[s0]+ya[s0+1]+ya[s0+65]+ya[s0+66])*0.25f;
            xb[r*33 + c] = px; yb[r*33 + c] = py;
            gx[(o1y+r)*256 + (o1x+c)] = px;
            gy[(o1y+r)*256 + (o1x+c)] = py;
        }
    }
    __syncthreads();
    // L2: 16x16 -> scale2
    {
        float* gx = (float*)g_px2 + (size_t)bc*128*128;
        float* gy = (float*)g_py2 + (size_t)bc*128*128;
        int o2y = oy >> 2, o2x = ox >> 2;
        if (tid < 16*16) {
            int r = tid >> 4, c = tid & 15;
            int s0 = (2*r)*33 + 2*c;
            float px = (xb[s0]+xb[s0+1]+xb[s0+33]+xb[s0+34])*0.25f;
            float py = (yb[s0]+yb[s0+1]+yb[s0+33]+yb[s0+34])*0.25f;
            xc[r*17 + c] = px; yc[r*17 + c] = py;
            gx[(o2y+r)*128 + (o2x+c)] = px;
            gy[(o2y+r)*128 + (o2x+c)] = py;
        }
    }
    __syncthreads();
    // L3: 8x8 -> scale3
    {
        float* gx = (float*)g_px3 + (size_t)bc*64*64;
        float* gy = (float*)g_py3 + (size_t)bc*64*64;
        int o3y = oy >> 3, o3x = ox >> 3;
        if (tid < 64) {
            int r = tid >> 3, c = tid & 7;
            int s0 = (2*r)*17 + 2*c;
            float px = (xc[s0]+xc[s0+1]+xc[s0+17]+xc[s0+18])*0.25f;
            float py = (yc[s0]+yc[s0+1]+yc[s0+17]+yc[s0+18])*0.25f;
            xd[r*9 + c] = px; yd[r*9 + c] = py;
            gx[(o3y+r)*64 + (o3x+c)] = px;
            gy[(o3y+r)*64 + (o3x+c)] = py;
        }
    }
    __syncthreads();
    // L4: 4x4 -> scale4
    {
        float* gx = (float*)g_px4 + (size_t)bc*32*32;
        float* gy = (float*)g_py4 + (size_t)bc*32*32;
        int o4y = oy >> 4, o4x = ox >> 4;
        if (tid < 16) {
            int r = tid >> 2, c = tid & 3;
            int s0 = (2*r)*9 + 2*c;
            gx[(o4y+r)*32 + (o4x+c)] = (xd[s0]+xd[s0+1]+xd[s0+9]+xd[s0+10])*0.25f;
            gy[(o4y+r)*32 + (o4x+c)] = (yd[s0]+yd[s0+1]+yd[s0+9]+yd[s0+10])*0.25f;
        }
    }
}

// ---------------------------------------------------------------------------
// SSIM tile body. S0: y one-hot from tgt, conv(y^2)==conv(y) drops yy plane.
template<bool S0>
__device__ __forceinline__ void ssim_tile(
    const float* __restrict__ xp, const float* __restrict__ yp,
    const int* __restrict__ tp, int cls,
    int Hs, int ty0, int tx0, int sidx, int bc,
    float (*sx)[SPITCH], float (*sy)[SPITCH], float* hbB,
    float* rss, float* rcs)
{
    constexpr float G[11] = {0.00102838f,0.00759870f,0.03600080f,0.10936070f,
                             0.21300560f,0.26601180f,0.21300560f,0.10936070f,
                             0.03600080f,0.00759870f,0.00102838f};
    const int OH = Hs - 10;
    int tid = threadIdx.x;
    float* hb0 = hbB;
    float* hb1 = hb0 + TIN*HPITCH;
    float* hb2 = hb1 + TIN*HPITCH;
    float* hb4 = hb2 + TIN*HPITCH;
    float* hb3 = hb4 + TIN*HPITCH;

    // Load (TIN x TIN) tile, zero-fill outside.
    for (int i = tid; i < TIN*TIN; i += NTHR) {
        int r = i / TIN, c = i - r*TIN;
        int ih = ty0 + r, iw = tx0 + c;
        float xv = 0.f, yv = 0.f;
        if (ih < Hs && iw < Hs) {
            int o = ih*Hs + iw;
            xv = xp[o];
            yv = S0 ? ((tp[o] == cls) ? 1.f : 0.f) : yp[o];
        }
        sx[r][c] = xv; sy[r][c] = yv;
    }
    __syncthreads();

    // Stage 1: horizontal blur, strips of 4 cols. 336 tasks.
    for (int task = tid; task < TIN*8; task += NTHR) {
        int r  = task >> 3;
        int c0 = (task & 7) << 2;
        float a0[4]={0,0,0,0}, a1[4]={0,0,0,0}, a2[4]={0,0,0,0};
        float a3[4]={0,0,0,0}, a4[4]={0,0,0,0};
#pragma unroll
        for (int i = 0; i < 14; i++) {
            float x = sx[r][c0+i], y = sy[r][c0+i];
            float xx = x*x, xy = x*y;
            float yy = S0 ? 0.f : y*y;
#pragma unroll
            for (int j = 0; j < 4; j++) {
                int k = i - j;
                if (k >= 0 && k < 11) {
                    a0[j] = fmaf(G[k], x,  a0[j]);
                    a1[j] = fmaf(G[k], y,  a1[j]);
                    a2[j] = fmaf(G[k], xx, a2[j]);
                    if (!S0) a3[j] = fmaf(G[k], yy, a3[j]);
                    a4[j] = fmaf(G[k], xy, a4[j]);
                }
            }
        }
        int o = r*HPITCH + c0;
#pragma unroll
        for (int j = 0; j < 4; j++) {
            hb0[o+j]=a0[j]; hb1[o+j]=a1[j]; hb2[o+j]=a2[j]; hb4[o+j]=a4[j];
            if (!S0) hb3[o+j]=a3[j];
        }
    }
    __syncthreads();

    // Stage 2: vertical blur + SSIM, strips of 4 rows. 256 tasks.
    float lss = 0.f, lcs = 0.f;
    {
        int c  = tid & 31;
        int r0 = (tid >> 5) << 2;
        float m1[4]={0,0,0,0}, m2[4]={0,0,0,0}, e11[4]={0,0,0,0};
        float e22[4]={0,0,0,0}, e12[4]={0,0,0,0};
#pragma unroll
        for (int i = 0; i < 14; i++) {
            int o = (r0+i)*HPITCH + c;
            float v0 = hb0[o], v1 = hb1[o], v2 = hb2[o], v4 = hb4[o];
            float v3 = S0 ? 0.f : hb3[o];
#pragma unroll
            for (int j = 0; j < 4; j++) {
                int k = i - j;
                if (k >= 0 && k < 11) {
                    m1[j]  = fmaf(G[k], v0, m1[j]);
                    m2[j]  = fmaf(G[k], v1, m2[j]);
                    e11[j] = fmaf(G[k], v2, e11[j]);
                    if (!S0) e22[j] = fmaf(G[k], v3, e22[j]);
                    e12[j] = fmaf(G[k], v4, e12[j]);
                }
            }
        }
        int ow = tx0 + c;
#pragma unroll
        for (int j = 0; j < 4; j++) {
            int oh = ty0 + r0 + j;
            if (oh < OH && ow < OH) {
                float M1 = m1[j], M2 = m2[j];
                float E22 = S0 ? M2 : e22[j];
                float m11 = M1*M1, m22 = M2*M2, m12 = M1*M2;
                float v1 = e11[j] - m11, v2 = E22 - m22, cov = e12[j] - m12;
                float cs = __fdividef(2.f*cov + 0.0009f, v1 + v2 + 0.0009f);
                float sv = __fdividef(2.f*m12 + 0.0001f, m11 + m22 + 0.0001f) * cs;
                lss += sv; lcs += cs;
            }
        }
    }

#pragma unroll
    for (int o = 16; o; o >>= 1) {
        lss += __shfl_down_sync(0xffffffffu, lss, o);
        lcs += __shfl_down_sync(0xffffffffu, lcs, o);
    }
    if ((tid & 31) == 0) { rss[tid>>5] = lss; rcs[tid>>5] = lcs; }
    __syncthreads();
    if (tid == 0) {
        float ts = 0.f, tc = 0.f;
#pragma unroll
        for (int w = 0; w < NTHR/32; w++) { ts += rss[w]; tc += rcs[w]; }
        atomicAdd(&g_ss[sidx*NBC + bc], ts);
        atomicAdd(&g_cs[sidx*NBC + bc], tc);
    }
}

// ---------------------------------------------------------------------------
// One launch, every tile of every scale. Block-index decode by scale ranges.
// scale0: 12288 blocks, s1: 3072, s2: 768, s3: 192, s4: 48 -> 16368 total.
__global__ __launch_bounds__(NTHR) void ssim_all(const int* __restrict__ tgt)
{
    __shared__ float sx[TIN][SPITCH];
    __shared__ float sy[TIN][SPITCH];
    __shared__ float hb[5*TIN*HPITCH];
    __shared__ float rss[NTHR/32], rcs[NTHR/32];

    int idx = blockIdx.x;
    int s, bc, ty, tx;
    if (idx < 12288)      { s=0; bc=idx>>8;  int t=idx&255;        ty=t>>4; tx=t&15; }
    else if (idx < 15360) { s=1; int r=idx-12288; bc=r>>6; int t=r&63; ty=t>>3; tx=t&7; }
    else if (idx < 16128) { s=2; int r=idx-15360; bc=r>>4; int t=r&15; ty=t>>2; tx=t&3; }
    else if (idx < 16320) { s=3; int r=idx-16128; bc=r>>2; int t=r&3;  ty=t>>1; tx=t&1; }
    else                  { s=4; bc=idx-16320; ty=0; tx=0; }

    int Hs = HH0 >> s;
    if (s == 0) {
        const float* xp = g_x0 + (size_t)bc*Hs*Hs;
        const int*   tp = tgt + (size_t)(bc/CC)*Hs*Hs;
        ssim_tile<true>(xp, nullptr, tp, bc%CC, Hs, ty*TS, tx*TS, 0, bc,
                        sx, sy, hb, rss, rcs);
    } else {
        const float* xp = pool_x(s) + (size_t)bc*Hs*Hs;
        const float* yp = pool_y(s) + (size_t)bc*Hs*Hs;
        ssim_tile<false>(xp, yp, nullptr, 0, Hs, ty*TS, tx*TS, s, bc,
                         sx, sy, hb, rss, rcs);
    }
}

// ---------------------------------------------------------------------------
__global__ void finalize(float* __restrict__ out)
{
    __shared__ float sm[NBC];
    int t = threadIdx.x;
    const float Wt[5]  = {0.0448f, 0.2856f, 0.3001f, 0.2363f, 0.1333f};
    const float cnt[5] = {502.f*502.f, 246.f*246.f, 118.f*118.f, 54.f*54.f, 22.f*22.f};
    if (t < NBC) {
        float ms = 1.f;
#pragma unroll
        for (int s = 0; s < NSCALES; s++) {
            float acc = (s == NSCALES-1) ? g_ss[s*NBC + t] : g_cs[s*NBC + t];
            float v = fmaxf(acc / cnt[s], 0.f);
            ms *= powf(v, Wt[s]);
        }
        sm[t] = ms;
    }
    __syncthreads();
    if (t == 0) {
        float a = 0.f;
#pragma unroll
        for (int i = 0; i < NBC; i++) a += sm[i];
        out[0] = 1.f - a / (float)NBC;
    }
}

// ---------------------------------------------------------------------------
extern "C" void kernel_launch(void* const* d_in, const int* in_sizes, int n_in,
                              void* d_out, int out_size)
{
    const float* pred = (const float*)d_in[0];
    const int*   tgt  = (const int*)d_in[1];
    float*       out  = (float*)d_out;

    int np = BB*HH0*HH0;
    softmax_x0<<<(np + 255)/256, 256>>>(pred);

    { dim3 g(8, 8, NBC); pool_pyramid<<<g, NTHR>>>(tgt); }

    ssim_all<<<16368, NTHR>>>(tgt);

    finalize<<<1, 64>>>(out);
}